// round 9
// baseline (speedup 1.0000x reference)
#include <cuda_runtime.h>
#include <cstdint>
#include <cstddef>

// ---------------------------------------------------------------------------
// TinyTransformer B=4 S=2048 D=512 V=32000 — legacy tf32 mma.sync.
// R8: 1 CTA/SM + full register budget (255) on the 128x128 GEMMs so ptxas can
// pipeline fragment loads across kk; 3-stage cp.async ring (wait_group 1);
// B-fragments preloaded per kk. Softmax smem-resident, minimal tail zeroing.
// ---------------------------------------------------------------------------

#define BATCH 4
#define SEQ   2048
#define DIM   512
#define VOCAB 32000
#define NQKV  1536
#define MTOK  8192

#define BM 128
#define BN 128
#define BK 32
#define AST 36     // bank(4g+t) bijective
#define BST 136    // bank(8t+g) bijective

__device__ float g_qkv[(size_t)MTOK * NQKV];
__device__ float g_scores[(size_t)BATCH * SEQ * SEQ];
__device__ float g_attn_out[(size_t)MTOK * DIM];
__device__ float g_embed_r[(size_t)VOCAB * DIM];
__device__ float g_qkvw_r[(size_t)DIM * NQKV];
__device__ float g_fcw_r[(size_t)DIM * VOCAB];

__device__ __forceinline__ uint32_t f2tf(float f) {
    uint32_t u;
    asm("cvt.rna.tf32.f32 %0, %1;" : "=r"(u) : "f"(f));
    return u;
}
__device__ __forceinline__ float rnd(float f) { return __uint_as_float(f2tf(f)); }

__device__ __forceinline__ void cpa16(void* s, const float* g) {
    uint32_t sa = (uint32_t)__cvta_generic_to_shared(s);
    asm volatile("cp.async.cg.shared.global [%0], [%1], 16;" :: "r"(sa), "l"(g));
}
#define CP_COMMIT() asm volatile("cp.async.commit_group;")
#define CP_WAIT0()  asm volatile("cp.async.wait_group 0;")
#define CP_WAIT1()  asm volatile("cp.async.wait_group 1;")

#define MMA_TF32(c, a, b0, b1)                                                 \
    asm volatile(                                                              \
        "mma.sync.aligned.m16n8k8.row.col.f32.tf32.tf32.f32 "                  \
        "{%0,%1,%2,%3},{%4,%5,%6,%7},{%8,%9},{%0,%1,%2,%3};"                   \
        : "+f"(c[0]), "+f"(c[1]), "+f"(c[2]), "+f"(c[3])                       \
        : "r"(a[0]), "r"(a[1]), "r"(a[2]), "r"(a[3]), "r"(b0), "r"(b1));

#define ACC_INIT()                                                             \
    float acc[2][8][4];                                                        \
    _Pragma("unroll")                                                          \
    for (int i = 0; i < 2; i++)                                                \
        _Pragma("unroll")                                                      \
        for (int j = 0; j < 8; j++)                                            \
            _Pragma("unroll")                                                  \
            for (int k = 0; k < 4; k++) acc[i][j][k] = 0.f;

// One BK=32 tile; all fragment loads for a kk grouped before the MMAs.
#define TILE_COMPUTE_KN(As, Bs)                                                \
    _Pragma("unroll")                                                          \
    for (int kk = 0; kk < 4; kk++) {                                           \
        uint32_t bf[8][2];                                                     \
        _Pragma("unroll")                                                      \
        for (int ni = 0; ni < 8; ni++) {                                       \
            bf[ni][0] = (Bs)[(kk * 8 + t) * BST + wn + ni * 8 + g];            \
            bf[ni][1] = (Bs)[(kk * 8 + t + 4) * BST + wn + ni * 8 + g];        \
        }                                                                      \
        uint32_t af[2][4];                                                     \
        _Pragma("unroll")                                                      \
        for (int mi = 0; mi < 2; mi++) {                                       \
            int mr = wm + mi * 16 + g;                                         \
            af[mi][0] = (As)[mr * AST + kk * 8 + t];                           \
            af[mi][1] = (As)[(mr + 8) * AST + kk * 8 + t];                     \
            af[mi][2] = (As)[mr * AST + kk * 8 + t + 4];                       \
            af[mi][3] = (As)[(mr + 8) * AST + kk * 8 + t + 4];                 \
        }                                                                      \
        _Pragma("unroll")                                                      \
        for (int ni = 0; ni < 8; ni++) {                                       \
            MMA_TF32(acc[0][ni], af[0], bf[ni][0], bf[ni][1]);                 \
            MMA_TF32(acc[1][ni], af[1], bf[ni][0], bf[ni][1]);                 \
        }                                                                      \
    }

#define TILE_COMPUTE_NK(As, Bs2)                                               \
    _Pragma("unroll")                                                          \
    for (int kk = 0; kk < 4; kk++) {                                           \
        uint32_t bf[8][2];                                                     \
        _Pragma("unroll")                                                      \
        for (int ni = 0; ni < 8; ni++) {                                       \
            int nr = wn + ni * 8 + g;                                          \
            bf[ni][0] = (Bs2)[nr * AST + kk * 8 + t];                          \
            bf[ni][1] = (Bs2)[nr * AST + kk * 8 + t + 4];                      \
        }                                                                      \
        uint32_t af[2][4];                                                     \
        _Pragma("unroll")                                                      \
        for (int mi = 0; mi < 2; mi++) {                                       \
            int mr = wm + mi * 16 + g;                                         \
            af[mi][0] = (As)[mr * AST + kk * 8 + t];                           \
            af[mi][1] = (As)[(mr + 8) * AST + kk * 8 + t];                     \
            af[mi][2] = (As)[mr * AST + kk * 8 + t + 4];                       \
            af[mi][3] = (As)[(mr + 8) * AST + kk * 8 + t + 4];                 \
        }                                                                      \
        _Pragma("unroll")                                                      \
        for (int ni = 0; ni < 8; ni++) {                                       \
            MMA_TF32(acc[0][ni], af[0], bf[ni][0], bf[ni][1]);                 \
            MMA_TF32(acc[1][ni], af[1], bf[ni][0], bf[ni][1]);                 \
        }                                                                      \
    }

#define STAGE_A_ASY(DST, NT, PTR_EXPR)                                         \
    _Pragma("unroll")                                                          \
    for (int i = 0; i < (128 * 32 / 4) / NT; i++) {                            \
        int v = tid + i * NT, r = v >> 3, kv = (v & 7) * 4;                    \
        cpa16((DST) + r * AST + kv, PTR_EXPR);                                 \
    }
#define STAGE_B_ASY(DST, NT, PTR_EXPR)                                         \
    _Pragma("unroll")                                                          \
    for (int i = 0; i < (32 * 128 / 4) / NT; i++) {                            \
        int v = tid + i * NT, r = v >> 5, nv = (v & 31) * 4;                   \
        cpa16((DST) + r * BST + nv, PTR_EXPR);                                 \
    }
#define STAGE_B_NK_ASY(DST, NT, PTR_EXPR)                                      \
    _Pragma("unroll")                                                          \
    for (int i = 0; i < (128 * 32 / 4) / NT; i++) {                            \
        int v = tid + i * NT, r = v >> 3, kv = (v & 7) * 4;                    \
        cpa16((DST) + r * AST + kv, PTR_EXPR);                                 \
    }

// ---------------------------------------------------------------------------
// 0) round pre-pass
// ---------------------------------------------------------------------------
__global__ __launch_bounds__(256)
void round_kernel(const float* __restrict__ src, float* __restrict__ dst, int n4)
{
    int i = blockIdx.x * 256 + threadIdx.x;
    if (i < n4) {
        float4 f = ((const float4*)src)[i];
        ((uint4*)dst)[i] = make_uint4(f2tf(f.x), f2tf(f.y), f2tf(f.z), f2tf(f.w));
    }
}

// ---------------------------------------------------------------------------
// 1) qkv = gather(embed_r, x) @ qkvw_r + b    M=8192 N=1536 K=512
//    3-stage cp.async ring, 1 CTA/SM, full register budget.
// ---------------------------------------------------------------------------
__global__ __launch_bounds__(256, 1)
void qkv_kernel(const int* __restrict__ x, const float* __restrict__ bias)
{
    extern __shared__ uint32_t sm[];
    int*      rows = (int*)sm;
    uint32_t* Ab   = sm + 128;                 // 3 * BM*AST
    uint32_t* Bb   = Ab + 3 * BM * AST;        // 3 * BK*BST
    const int tid = threadIdx.x;
    const int lane = tid & 31, wid = tid >> 5;
    const int wm = (wid & 3) * 32, wn = (wid >> 2) * 64;
    const int g = lane >> 2, t = lane & 3;
    ACC_INIT();
    const int m0 = blockIdx.y * BM;
    const int n0 = blockIdx.x * BN;
    if (tid < BM) rows[tid] = x[m0 + tid];
    __syncthreads();

    #pragma unroll
    for (int p = 0; p < 2; p++) {
        STAGE_A_ASY(Ab + p * BM * AST, 256,
                    g_embed_r + (size_t)rows[r] * DIM + p * BK + kv);
        STAGE_B_ASY(Bb + p * BK * BST, 256,
                    g_qkvw_r + (size_t)(p * BK + r) * NQKV + n0 + nv);
        CP_COMMIT();
    }
    for (int c = 0; c < 16; c++) {
        const int cur = c % 3;
        CP_WAIT1();
        __syncthreads();
        if (c + 2 < 16) {
            const int nxt = (c + 2) % 3;
            const int k1 = (c + 2) * BK;
            STAGE_A_ASY(Ab + nxt * BM * AST, 256,
                        g_embed_r + (size_t)rows[r] * DIM + k1 + kv);
            STAGE_B_ASY(Bb + nxt * BK * BST, 256,
                        g_qkvw_r + (size_t)(k1 + r) * NQKV + n0 + nv);
        }
        CP_COMMIT();   // keep group count in lockstep even on last chunks
        TILE_COMPUTE_KN(Ab + cur * BM * AST, Bb + cur * BK * BST);
    }
    #pragma unroll
    for (int mi = 0; mi < 2; mi++)
        #pragma unroll
        for (int ni = 0; ni < 8; ni++) {
            int r0 = m0 + wm + mi * 16 + g;
            int c  = n0 + wn + ni * 8 + t * 2;
            float b0 = bias[c], b1 = bias[c + 1];
            float* p0 = g_qkv + (size_t)r0 * NQKV + c;
            float* p1 = g_qkv + (size_t)(r0 + 8) * NQKV + c;
            *(float2*)p0 = make_float2(rnd(acc[mi][ni][0] + b0),
                                       rnd(acc[mi][ni][1] + b1));
            *(float2*)p1 = make_float2(rnd(acc[mi][ni][2] + b0),
                                       rnd(acc[mi][ni][3] + b1));
        }
}

// ---------------------------------------------------------------------------
// 2) scores = Q @ K^T * scale   (lower-triangular blocks only)
// ---------------------------------------------------------------------------
__global__ __launch_bounds__(256, 1)
void scores_kernel()
{
    if (blockIdx.x > blockIdx.y) return;
    extern __shared__ uint32_t sm[];
    uint32_t* Ab = sm;                       // 3 * BM*AST
    uint32_t* Bb = Ab + 3 * BM * AST;        // 3 * BM*AST (n-major)
    const int tid = threadIdx.x;
    const int lane = tid & 31, wid = tid >> 5;
    const int wm = (wid & 3) * 32, wn = (wid >> 2) * 64;
    const int g = lane >> 2, t = lane & 3;
    ACC_INIT();
    const int b  = blockIdx.z;
    const int q0 = blockIdx.y * BM;
    const int n0 = blockIdx.x * BN;
    const float* Q = g_qkv + (size_t)(b * SEQ) * NQKV;
    const float* K = Q + DIM;

    #pragma unroll
    for (int p = 0; p < 2; p++) {
        STAGE_A_ASY(Ab + p * BM * AST, 256,
                    Q + (size_t)(q0 + r) * NQKV + p * BK + kv);
        STAGE_B_NK_ASY(Bb + p * BM * AST, 256,
                       K + (size_t)(n0 + r) * NQKV + p * BK + kv);
        CP_COMMIT();
    }
    for (int c = 0; c < 16; c++) {
        const int cur = c % 3;
        CP_WAIT1();
        __syncthreads();
        if (c + 2 < 16) {
            const int nxt = (c + 2) % 3;
            const int k1 = (c + 2) * BK;
            STAGE_A_ASY(Ab + nxt * BM * AST, 256,
                        Q + (size_t)(q0 + r) * NQKV + k1 + kv);
            STAGE_B_NK_ASY(Bb + nxt * BM * AST, 256,
                           K + (size_t)(n0 + r) * NQKV + k1 + kv);
        }
        CP_COMMIT();
        TILE_COMPUTE_NK(Ab + cur * BM * AST, Bb + cur * BM * AST);
    }
    const float scale = 0.044194173824159216f;
    #pragma unroll
    for (int mi = 0; mi < 2; mi++)
        #pragma unroll
        for (int ni = 0; ni < 8; ni++) {
            int r0 = q0 + wm + mi * 16 + g;
            int c  = n0 + wn + ni * 8 + t * 2;
            float* p0 = g_scores + (size_t)(b * SEQ + r0) * SEQ + c;
            float* p1 = p0 + (size_t)8 * SEQ;
            *(float2*)p0 = make_float2(acc[mi][ni][0] * scale, acc[mi][ni][1] * scale);
            *(float2*)p1 = make_float2(acc[mi][ni][2] * scale, acc[mi][ni][3] * scale);
        }
}

// ---------------------------------------------------------------------------
// 3) causal softmax, smem-resident exp; zero only the intra-tile masked strip
// ---------------------------------------------------------------------------
__global__ __launch_bounds__(256)
void softmax_kernel()
{
    const int row = blockIdx.x;
    const int q = row & (SEQ - 1);
    float* p = g_scores + (size_t)row * SEQ;
    const int L = q + 1;
    const int kend = (q & ~127) + 128;        // attnv reads only k < kend
    const int tid = threadIdx.x;
    const int lane = tid & 31, wid = tid >> 5;
    __shared__ float red[8];
    __shared__ float ebuf[SEQ];               // 8 KB exp stash

    float m = -1e30f;
    for (int k = tid; k < L; k += 256) {
        float v = p[k];
        ebuf[k] = v;
        m = fmaxf(m, v);
    }
    #pragma unroll
    for (int s = 16; s > 0; s >>= 1) m = fmaxf(m, __shfl_xor_sync(~0u, m, s));
    if (lane == 0) red[wid] = m;
    __syncthreads();
    m = red[lane & 7];
    #pragma unroll
    for (int s = 4; s > 0; s >>= 1) m = fmaxf(m, __shfl_xor_sync(~0u, m, s));

    float sum = 0.f;
    for (int k = tid; k < L; k += 256) {
        float e = __expf(ebuf[k] - m);
        ebuf[k] = e;
        sum += e;
    }
    #pragma unroll
    for (int s = 16; s > 0; s >>= 1) sum += __shfl_xor_sync(~0u, sum, s);
    __syncthreads();
    if (lane == 0) red[wid] = sum;
    __syncthreads();
    sum = red[lane & 7];
    #pragma unroll
    for (int s = 4; s > 0; s >>= 1) sum += __shfl_xor_sync(~0u, sum, s);

    const float inv = 1.0f / sum;
    for (int k = tid; k < L; k += 256) p[k] = rnd(ebuf[k] * inv);
    for (int k = L + tid; k < kend; k += 256) p[k] = 0.f;
}

// ---------------------------------------------------------------------------
// 4) out = attn @ V   (k truncated at causal boundary q0+128)
// ---------------------------------------------------------------------------
__global__ __launch_bounds__(256, 1)
void attnv_kernel()
{
    extern __shared__ uint32_t sm[];
    uint32_t* Ab = sm;
    uint32_t* Bb = Ab + 3 * BM * AST;
    const int tid = threadIdx.x;
    const int lane = tid & 31, wid = tid >> 5;
    const int wm = (wid & 3) * 32, wn = (wid >> 2) * 64;
    const int g = lane >> 2, t = lane & 3;
    ACC_INIT();
    const int b  = blockIdx.z;
    const int q0 = blockIdx.y * BM;
    const int n0 = blockIdx.x * BN;
    const float* A  = g_scores + (size_t)(b * SEQ) * SEQ;
    const float* Vm = g_qkv + (size_t)(b * SEQ) * NQKV + 2 * DIM;

    const int NC = (q0 + BM) / BK;
    #pragma unroll
    for (int p = 0; p < 2; p++) {
        if (p < NC) {
            STAGE_A_ASY(Ab + p * BM * AST, 256,
                        A + (size_t)(q0 + r) * SEQ + p * BK + kv);
            STAGE_B_ASY(Bb + p * BK * BST, 256,
                        Vm + (size_t)(p * BK + r) * NQKV + n0 + nv);
        }
        CP_COMMIT();
    }
    for (int c = 0; c < NC; c++) {
        const int cur = c % 3;
        CP_WAIT1();
        __syncthreads();
        if (c + 2 < NC) {
            const int nxt = (c + 2) % 3;
            const int k1 = (c + 2) * BK;
            STAGE_A_ASY(Ab + nxt * BM * AST, 256,
                        A + (size_t)(q0 + r) * SEQ + k1 + kv);
            STAGE_B_ASY(Bb + nxt * BK * BST, 256,
                        Vm + (size_t)(k1 + r) * NQKV + n0 + nv);
        }
        CP_COMMIT();
        TILE_COMPUTE_KN(Ab + cur * BM * AST, Bb + cur * BK * BST);
    }
    #pragma unroll
    for (int mi = 0; mi < 2; mi++)
        #pragma unroll
        for (int ni = 0; ni < 8; ni++) {
            int r0 = q0 + wm + mi * 16 + g;
            int c  = n0 + wn + ni * 8 + t * 2;
            float* p0 = g_attn_out + (size_t)(b * SEQ + r0) * DIM + c;
            float* p1 = p0 + (size_t)8 * DIM;
            *(float2*)p0 = make_float2(rnd(acc[mi][ni][0]), rnd(acc[mi][ni][1]));
            *(float2*)p1 = make_float2(rnd(acc[mi][ni][2]), rnd(acc[mi][ni][3]));
        }
}

// ---------------------------------------------------------------------------
// 5) logits = attn_out @ fcw_r + fc_b    M=8192 N=32000 K=512
//    256x128 tile, 512 threads, BK=64, 2-stage; B fragments preloaded.
// ---------------------------------------------------------------------------
#define LBM  256
#define LBK  64
#define LAST 68

__global__ __launch_bounds__(512, 1)
void logits_kernel(const float* __restrict__ bias, float* __restrict__ out)
{
    extern __shared__ uint32_t sm[];
    uint32_t* Ab = sm;                        // 2 * LBM*LAST
    uint32_t* Bb = Ab + 2 * LBM * LAST;       // 2 * LBK*BST
    const int tid = threadIdx.x;
    const int lane = tid & 31, wid = tid >> 5;
    const int wm = (wid & 7) * 32, wn = (wid >> 3) * 64;
    const int g = lane >> 2, t = lane & 3;
    ACC_INIT();
    const int m0 = blockIdx.y * LBM;
    const int n0 = blockIdx.x * BN;

    #pragma unroll
    for (int i = 0; i < 8; i++) {
        int v = tid + i * 512, r = v >> 4, kv = (v & 15) * 4;
        cpa16(Ab + r * LAST + kv, g_attn_out + (size_t)(m0 + r) * DIM + kv);
    }
    #pragma unroll
    for (int i = 0; i < 4; i++) {
        int v = tid + i * 512, r = v >> 5, nv = (v & 31) * 4;
        cpa16(Bb + r * BST + nv, g_fcw_r + (size_t)r * VOCAB + n0 + nv);
    }
    CP_COMMIT();

    for (int c = 0; c < 8; c++) {
        const int bf_ = c & 1;
        CP_WAIT0();
        __syncthreads();
        if (c + 1 < 8) {
            const int k1 = (c + 1) * LBK;
            uint32_t* An = Ab + (bf_ ^ 1) * LBM * LAST;
            uint32_t* Bn = Bb + (bf_ ^ 1) * LBK * BST;
            #pragma unroll
            for (int i = 0; i < 8; i++) {
                int v = tid + i * 512, r = v >> 4, kv = (v & 15) * 4;
                cpa16(An + r * LAST + kv,
                      g_attn_out + (size_t)(m0 + r) * DIM + k1 + kv);
            }
            #pragma unroll
            for (int i = 0; i < 4; i++) {
                int v = tid + i * 512, r = v >> 5, nv = (v & 31) * 4;
                cpa16(Bn + r * BST + nv,
                      g_fcw_r + (size_t)(k1 + r) * VOCAB + n0 + nv);
            }
            CP_COMMIT();
        }
        const uint32_t* As = Ab + bf_ * LBM * LAST;
        const uint32_t* Bs = Bb + bf_ * LBK * BST;
        #pragma unroll
        for (int kk = 0; kk < 8; kk++) {
            uint32_t bfr[8][2];
            #pragma unroll
            for (int ni = 0; ni < 8; ni++) {
                bfr[ni][0] = Bs[(kk * 8 + t) * BST + wn + ni * 8 + g];
                bfr[ni][1] = Bs[(kk * 8 + t + 4) * BST + wn + ni * 8 + g];
            }
            uint32_t af[2][4];
            #pragma unroll
            for (int mi = 0; mi < 2; mi++) {
                int mr = wm + mi * 16 + g;
                af[mi][0] = As[mr * LAST + kk * 8 + t];
                af[mi][1] = As[(mr + 8) * LAST + kk * 8 + t];
                af[mi][2] = As[mr * LAST + kk * 8 + t + 4];
                af[mi][3] = As[(mr + 8) * LAST + kk * 8 + t + 4];
            }
            #pragma unroll
            for (int ni = 0; ni < 8; ni++) {
                MMA_TF32(acc[0][ni], af[0], bfr[ni][0], bfr[ni][1]);
                MMA_TF32(acc[1][ni], af[1], bfr[ni][0], bfr[ni][1]);
            }
        }
    }
    #pragma unroll
    for (int mi = 0; mi < 2; mi++)
        #pragma unroll
        for (int ni = 0; ni < 8; ni++) {
            int r0 = m0 + wm + mi * 16 + g;
            int c  = n0 + wn + ni * 8 + t * 2;
            float b0 = bias[c], b1 = bias[c + 1];
            float* p0 = out + (size_t)r0 * VOCAB + c;
            float* p1 = out + (size_t)(r0 + 8) * VOCAB + c;
            *(float2*)p0 = make_float2(acc[mi][ni][0] + b0, acc[mi][ni][1] + b1);
            *(float2*)p1 = make_float2(acc[mi][ni][2] + b0, acc[mi][ni][3] + b1);
        }
}

// ---------------------------------------------------------------------------
extern "C" void kernel_launch(void* const* d_in, const int* in_sizes, int n_in,
                              void* d_out, int out_size)
{
    (void)in_sizes; (void)n_in; (void)out_size;
    const int*   x     = (const int*)  d_in[0];
    const float* embed = (const float*)d_in[1];
    const float* qkv_w = (const float*)d_in[2];
    const float* qkv_b = (const float*)d_in[3];
    const float* fc_w  = (const float*)d_in[4];
    const float* fc_b  = (const float*)d_in[5];
    float* out = (float*)d_out;

    const int smem_qkv    = (128 + 3 * BM * AST + 3 * BK * BST) * 4;  // ~108 KB
    const int smem_scores = (3 * BM * AST + 3 * BM * AST) * 4;        // ~110 KB
    const int smem_attnv  = (3 * BM * AST + 3 * BK * BST) * 4;        // ~107 KB
    const int smem_logits = (2 * LBM * LAST + 2 * LBK * BST) * 4;     // ~209 KB

    cudaFuncSetAttribute(qkv_kernel,
        cudaFuncAttributeMaxDynamicSharedMemorySize, smem_qkv);
    cudaFuncSetAttribute(scores_kernel,
        cudaFuncAttributeMaxDynamicSharedMemorySize, smem_scores);
    cudaFuncSetAttribute(attnv_kernel,
        cudaFuncAttributeMaxDynamicSharedMemorySize, smem_attnv);
    cudaFuncSetAttribute(logits_kernel,
        cudaFuncAttributeMaxDynamicSharedMemorySize, smem_logits);

    float* emb_dst;  cudaGetSymbolAddress((void**)&emb_dst,  g_embed_r);
    float* qkvw_dst; cudaGetSymbolAddress((void**)&qkvw_dst, g_qkvw_r);
    float* fcw_dst;  cudaGetSymbolAddress((void**)&fcw_dst,  g_fcw_r);
    const int n4_emb  = VOCAB * DIM / 4;
    const int n4_qkvw = DIM * NQKV / 4;
    const int n4_fcw  = DIM * VOCAB / 4;
    round_kernel<<<(n4_emb  + 255) / 256, 256>>>(embed, emb_dst,  n4_emb);
    round_kernel<<<(n4_qkvw + 255) / 256, 256>>>(qkv_w, qkvw_dst, n4_qkvw);
    round_kernel<<<(n4_fcw  + 255) / 256, 256>>>(fc_w,  fcw_dst,  n4_fcw);

    qkv_kernel    <<<dim3(NQKV / BN, MTOK / BM), 256, smem_qkv>>>(x, qkv_b);
    scores_kernel <<<dim3(SEQ / BN, SEQ / BM, BATCH), 256, smem_scores>>>();
    softmax_kernel<<<MTOK, 256>>>();
    attnv_kernel  <<<dim3(DIM / BN, SEQ / BM, BATCH), 256, smem_attnv>>>();
    logits_kernel <<<dim3(VOCAB / BN, MTOK / LBM), 512, smem_logits>>>(fc_b, out);
}